// round 11
// baseline (speedup 1.0000x reference)
#include <cuda_runtime.h>
#include <cuda_bf16.h>
#include <math.h>
#include <stdint.h>

// Problem dims (fixed)
#define Vv 32000
#define Dd 1024
#define Bb 8
#define Tt 256
#define Mrows (Bb * Tt)   // 2048

// ---------------- scratch (static device globals; allocation-free) ----------
__device__ __nv_bfloat16 g_Xb[Mrows * Dd];
__device__ __nv_bfloat16 g_Wb[Dd * Dd];
__device__ __nv_bfloat16 g_Ub[Dd * Dd];
__device__ __nv_bfloat16 g_Woutb[(size_t)Vv * Dd];
__device__ float g_Wx[Mrows * Dd];
__device__ __nv_bfloat16 g_hsb[Mrows * Dd];

// ---------------- PTX helpers ----------------------------------------------
__device__ __forceinline__ uint32_t smem_u32(const void* p) {
    uint32_t a;
    asm("{ .reg .u64 t; cvta.to.shared.u64 t, %1; cvt.u32.u64 %0, t; }"
        : "=r"(a) : "l"(p));
    return a;
}

__device__ __forceinline__ void cp_async16(uint32_t dst, const void* src) {
    asm volatile("cp.async.cg.shared.global [%0], [%1], 16;" :: "r"(dst), "l"(src));
}
#define CP_COMMIT() asm volatile("cp.async.commit_group;" ::: "memory")
#define CP_WAIT(n)  asm volatile("cp.async.wait_group %0;" :: "n"(n) : "memory")

__device__ __forceinline__ void ldsm_x4(uint32_t& r0, uint32_t& r1,
                                        uint32_t& r2, uint32_t& r3, uint32_t addr) {
    asm volatile("ldmatrix.sync.aligned.m8n8.x4.shared.b16 {%0,%1,%2,%3}, [%4];"
                 : "=r"(r0), "=r"(r1), "=r"(r2), "=r"(r3) : "r"(addr));
}

__device__ __forceinline__ void mma16816(float& c0, float& c1, float& c2, float& c3,
                                         uint32_t a0, uint32_t a1, uint32_t a2, uint32_t a3,
                                         uint32_t b0, uint32_t b1) {
    asm volatile(
        "mma.sync.aligned.m16n8k16.row.col.f32.bf16.bf16.f32 "
        "{%0,%1,%2,%3}, {%4,%5,%6,%7}, {%8,%9}, {%0,%1,%2,%3};\n"
        : "+f"(c0), "+f"(c1), "+f"(c2), "+f"(c3)
        : "r"(a0), "r"(a1), "r"(a2), "r"(a3), "r"(b0), "r"(b1));
}

#define CLUSTER_SYNC() do { \
    asm volatile("barrier.cluster.arrive.aligned;" ::: "memory"); \
    asm volatile("barrier.cluster.wait.aligned;" ::: "memory"); \
} while (0)

// ---------------- small helpers --------------------------------------------
__global__ void f32_to_bf16_kernel(const float4* __restrict__ src,
                                   __nv_bfloat162* __restrict__ dst, int n4) {
    for (int i = blockIdx.x * blockDim.x + threadIdx.x; i < n4;
         i += gridDim.x * blockDim.x) {
        float4 v = src[i];
        dst[2 * i]     = __floats2bfloat162_rn(v.x, v.y);
        dst[2 * i + 1] = __floats2bfloat162_rn(v.z, v.w);
    }
}

__global__ void gather_embed_kernel(const int* __restrict__ idx,
                                    const float* __restrict__ E,
                                    __nv_bfloat16* __restrict__ Xb) {
    int row = blockIdx.x;
    int v = idx[row];
    const float4* src = (const float4*)(E + (size_t)v * Dd);
    __nv_bfloat162* dst = (__nv_bfloat162*)(Xb + (size_t)row * Dd);
    for (int i = threadIdx.x; i < Dd / 4; i += blockDim.x) {
        float4 a = src[i];
        dst[2 * i]     = __floats2bfloat162_rn(a.x, a.y);
        dst[2 * i + 1] = __floats2bfloat162_rn(a.z, a.w);
    }
}

// ---------------- pipelined HMMA GEMM:  C[M,N] = A[M,K]*B[N,K]^T + bias[N] --
#define ROWB 80
#define A_BYTES (128 * ROWB)
#define STG (2 * A_BYTES)
#define S_ST 3
#define GEMM_SMEM (S_ST * STG + 128)

__device__ __forceinline__ void load_stage(const __nv_bfloat16* Ag,
                                           const __nv_bfloat16* Bg, int K,
                                           int kt, uint32_t base, int tid) {
    const int kbase = kt * 32;
#pragma unroll
    for (int i = 0; i < 2; i++) {
        int id = tid + i * 256;
        int row = id >> 2, seg = id & 3;
        uint32_t soff = row * ROWB + seg * 16;
        cp_async16(base + soff, Ag + (size_t)row * K + kbase + seg * 8);
        cp_async16(base + A_BYTES + soff, Bg + (size_t)row * K + kbase + seg * 8);
    }
}

__global__ __launch_bounds__(256, 2)
void gemm_bf16_kernel(const __nv_bfloat16* __restrict__ A,
                      const __nv_bfloat16* __restrict__ Bm,
                      const float* __restrict__ bias,
                      float* __restrict__ C, int M, int N, int K) {
    extern __shared__ char dsm[];
    uint32_t sb = (smem_u32(dsm) + 127) & ~127u;

    const int tid = threadIdx.x;
    const int warp = tid >> 5, lane = tid & 31;
    const int wm = warp >> 2, wn = warp & 3;
    const int bm = blockIdx.x, bn = blockIdx.y;
    const int NT = K / 32;

    const uint32_t aLane = (uint32_t)((lane & 15) * ROWB + ((lane >> 4) << 4));
    const uint32_t bLane = (uint32_t)((((lane >> 4) << 3) + (lane & 7)) * ROWB +
                                      (((lane >> 3) & 1) << 4));

    float acc[4][4][4];
#pragma unroll
    for (int mi = 0; mi < 4; mi++)
#pragma unroll
        for (int ni = 0; ni < 4; ni++)
#pragma unroll
            for (int q = 0; q < 4; q++) acc[mi][ni][q] = 0.f;

    const __nv_bfloat16* Ag = A + (size_t)(bm * 128) * K;
    const __nv_bfloat16* Bg = Bm + (size_t)(bn * 128) * K;

    load_stage(Ag, Bg, K, 0, sb, tid);
    CP_COMMIT();
    load_stage(Ag, Bg, K, 1, sb + STG, tid);
    CP_COMMIT();

    for (int kt = 0; kt < NT; kt++) {
        CP_WAIT(1);
        __syncthreads();

        const int ktn = kt + 2;
        if (ktn < NT)
            load_stage(Ag, Bg, K, ktn, sb + (ktn % S_ST) * STG, tid);
        CP_COMMIT();

        const uint32_t stage = sb + (kt % S_ST) * STG;
        const uint32_t aBase = stage + (wm * 64) * ROWB + aLane;
        const uint32_t bBase = stage + A_BYTES + (wn * 32) * ROWB + bLane;

#pragma unroll
        for (int ks = 0; ks < 64; ks += 32) {
            uint32_t af[4][4], bf[2][4];
#pragma unroll
            for (int mi = 0; mi < 4; mi++)
                ldsm_x4(af[mi][0], af[mi][1], af[mi][2], af[mi][3],
                        aBase + mi * 16 * ROWB + ks);
#pragma unroll
            for (int nb = 0; nb < 2; nb++)
                ldsm_x4(bf[nb][0], bf[nb][1], bf[nb][2], bf[nb][3],
                        bBase + nb * 16 * ROWB + ks);
#pragma unroll
            for (int mi = 0; mi < 4; mi++)
#pragma unroll
                for (int nj = 0; nj < 4; nj++)
                    mma16816(acc[mi][nj][0], acc[mi][nj][1],
                             acc[mi][nj][2], acc[mi][nj][3],
                             af[mi][0], af[mi][1], af[mi][2], af[mi][3],
                             bf[nj >> 1][(nj & 1) * 2], bf[nj >> 1][(nj & 1) * 2 + 1]);
        }
    }

    const int g = lane >> 2, tq = lane & 3;
#pragma unroll
    for (int ni = 0; ni < 4; ni++) {
        int col = bn * 128 + wn * 32 + ni * 8 + tq * 2;
        float b0 = bias[col], b1 = bias[col + 1];
#pragma unroll
        for (int mi = 0; mi < 4; mi++) {
            int row = bm * 128 + wm * 64 + mi * 16 + g;
            *(float2*)&C[(size_t)row * N + col] =
                make_float2(acc[mi][ni][0] + b0, acc[mi][ni][1] + b1);
            *(float2*)&C[(size_t)(row + 8) * N + col] =
                make_float2(acc[mi][ni][2] + b0, acc[mi][ni][3] + b1);
        }
    }
}

// ---------------- cluster-resident RNN recurrence ---------------------------
// 8 clusters (one per batch) x 16 CTAs x 512 threads. CTA rank cr owns rows
// [cr*64, cr*64+64) of U (bf16 SMEM, 128 KB) and a full replicated h vector
// (fp32, double-buffered, 2 x 4 KB SMEM). Per step: SMEM dot products, warp
// butterfly reduce, DSMEM broadcast of the 64 new h values to all 16 CTAs,
// one cluster.sync. Zero global traffic in the recurrent loop.
#define USM_BYTES (64 * 1024 * 2)              // 131072
#define RNN_SMEM  (USM_BYTES + 2 * 1024 * 4)   // + two h buffers = 139264

__global__ __launch_bounds__(512, 1) __cluster_dims__(16, 1, 1)
void rnn_cluster_kernel(const float* __restrict__ Wx,
                        const float* __restrict__ bU,
                        __nv_bfloat16* __restrict__ hsb) {
    extern __shared__ char dsm[];
    const uint4*  Us  = (const uint4*)dsm;            // U rows: 64 x 128 uint4
    const float4* hsv = (const float4*)(dsm + USM_BYTES);

    const int tid = threadIdx.x;
    const int lane = tid & 31, w = tid >> 5;          // 16 warps
    const int b  = blockIdx.x >> 4;                   // batch = cluster id
    const int cr = blockIdx.x & 15;                   // cluster rank

    const uint32_t sbase  = smem_u32(dsm);
    const uint32_t hsBase = sbase + USM_BYTES;

    // mapa: lane L -> CTA L's h-buffer base (lanes 0..15)
    uint32_t peerHs = 0;
    if (lane < 16)
        asm("mapa.shared::cluster.u32 %0, %1, %2;"
            : "=r"(peerHs) : "r"(hsBase), "r"(lane));

    // load this CTA's 64 U rows (bf16, 128 KB) via cp.async
    {
        const char* src = (const char*)g_Ub + (size_t)cr * USM_BYTES;
        for (int i = tid; i < USM_BYTES / 16; i += 512)
            cp_async16(sbase + i * 16, src + i * 16);
        CP_COMMIT();
    }
    // zero h buffer 0 (local copy)
    if (tid < 256) ((float4*)(dsm + USM_BYTES))[tid] =
        make_float4(0.f, 0.f, 0.f, 0.f);
    CP_WAIT(0);
    __syncthreads();

    // per-output constants (lanes 0..3 of each warp produce rows w*4 + lane)
    const int myrow = cr * 64 + w * 4 + lane;   // valid for lane < 4
    const float bUv = (lane < 4) ? __ldg(&bU[myrow]) : 0.f;
    const float* WxB = Wx + (size_t)b * Tt * Dd;

    for (int t = 0; t < Tt; t++) {
        // prefetch Wx for this step's outputs (lanes 0..3)
        float wxv = 0.f;
        if (lane < 4) wxv = __ldg(&WxB[(size_t)t * Dd + myrow]);

        const float4* hv = hsv + (t & 1) * 256;
        float acc0 = 0.f, acc1 = 0.f, acc2 = 0.f, acc3 = 0.f;

        // lane handles cols {l*8 + k*256 .. +7}, rows w*4..w*4+3
#pragma unroll
        for (int k = 0; k < 4; k++) {
            const float4 ha = hv[k * 64 + lane * 2];
            const float4 hb = hv[k * 64 + lane * 2 + 1];
#pragma unroll
            for (int j = 0; j < 4; j++) {
                const uint4 uu = Us[(w * 4 + j) * 128 + k * 32 + lane];
                float f0 = __uint_as_float(uu.x << 16);
                float f1 = __uint_as_float(uu.x & 0xFFFF0000u);
                float f2 = __uint_as_float(uu.y << 16);
                float f3 = __uint_as_float(uu.y & 0xFFFF0000u);
                float f4 = __uint_as_float(uu.z << 16);
                float f5 = __uint_as_float(uu.z & 0xFFFF0000u);
                float f6 = __uint_as_float(uu.w << 16);
                float f7 = __uint_as_float(uu.w & 0xFFFF0000u);
                float s = f0 * ha.x + f1 * ha.y + f2 * ha.z + f3 * ha.w +
                          f4 * hb.x + f5 * hb.y + f6 * hb.z + f7 * hb.w;
                if (j == 0) acc0 += s;
                else if (j == 1) acc1 += s;
                else if (j == 2) acc2 += s;
                else acc3 += s;
            }
        }

        // butterfly reduce: row j total ends on lane j
        float myval = 0.f;
#pragma unroll
        for (int j = 0; j < 4; j++) {
            float v = (j == 0) ? acc0 : (j == 1) ? acc1 : (j == 2) ? acc2 : acc3;
            v += __shfl_xor_sync(0xffffffffu, v, 16);
            v += __shfl_xor_sync(0xffffffffu, v, 8);
            v += __shfl_xor_sync(0xffffffffu, v, 4);
            v += __shfl_xor_sync(0xffffffffu, v, 2);
            v += __shfl_xor_sync(0xffffffffu, v, 1);
            if (lane == j) myval = v;
        }

        float hn = 0.f;
        if (lane < 4) {
            hn = tanhf(myval + wxv + bUv);
            hsb[((size_t)b * Tt + t) * Dd + myrow] = __float2bfloat16(hn);
        }

        // broadcast the 4 new h values of this warp to all 16 cluster CTAs
        const uint32_t bufOff = (uint32_t)(((t + 1) & 1) * 4096);
#pragma unroll
        for (int j = 0; j < 4; j++) {
            float v = __shfl_sync(0xffffffffu, hn, j);
            if (lane < 16) {
                uint32_t addr = peerHs + bufOff +
                                (uint32_t)((cr * 64 + w * 4 + j) * 4);
                asm volatile("st.shared::cluster.f32 [%0], %1;"
                             :: "r"(addr), "f"(v) : "memory");
            }
        }

        CLUSTER_SYNC();
    }
}

// ---------------- fused log-softmax (SMEM-resident row) ---------------------
#define LSM_SMEM (Vv * 4)   // 128000 bytes

__global__ __launch_bounds__(256)
void logsoftmax_kernel(float* __restrict__ C) {
    extern __shared__ float rowbuf[];
    __shared__ float red[256];
    const int row = blockIdx.x, tid = threadIdx.x;
    float4* p4 = (float4*)(C + (size_t)row * Vv);
    float4* r4 = (float4*)rowbuf;

    float m = -1e30f;
    for (int i = tid; i < Vv / 4; i += 256) {
        float4 v = p4[i];
        r4[i] = v;
        m = fmaxf(m, fmaxf(fmaxf(v.x, v.y), fmaxf(v.z, v.w)));
    }
    red[tid] = m; __syncthreads();
    for (int s = 128; s > 0; s >>= 1) {
        if (tid < s) red[tid] = fmaxf(red[tid], red[tid + s]);
        __syncthreads();
    }
    m = red[0]; __syncthreads();

    float sum = 0.f;
    for (int i = tid; i < Vv / 4; i += 256) {
        float4 v = r4[i];
        sum += expf(v.x - m) + expf(v.y - m) + expf(v.z - m) + expf(v.w - m);
    }
    red[tid] = sum; __syncthreads();
    for (int s = 128; s > 0; s >>= 1) {
        if (tid < s) red[tid] += red[tid + s];
        __syncthreads();
    }
    float lse = m + logf(red[0]);
    __syncthreads();

    for (int i = tid; i < Vv / 4; i += 256) {
        float4 v = r4[i];
        v.x -= lse; v.y -= lse; v.z -= lse; v.w -= lse;
        p4[i] = v;
    }
}

// ---------------- launcher ---------------------------------------------------
extern "C" void kernel_launch(void* const* d_in, const int* in_sizes, int n_in,
                              void* d_out, int out_size) {
    const int*   idx  = (const int*)d_in[0];
    const float* E    = (const float*)d_in[1];
    const float* W    = (const float*)d_in[2];
    const float* bW   = (const float*)d_in[3];
    const float* U    = (const float*)d_in[4];
    const float* bU   = (const float*)d_in[5];
    const float* Wout = (const float*)d_in[6];
    const float* bout = (const float*)d_in[7];
    float* out = (float*)d_out;

    void* p;
    cudaGetSymbolAddress(&p, g_Xb);    __nv_bfloat16* Xb    = (__nv_bfloat16*)p;
    cudaGetSymbolAddress(&p, g_Wb);    __nv_bfloat16* Wb    = (__nv_bfloat16*)p;
    cudaGetSymbolAddress(&p, g_Ub);    __nv_bfloat16* Ub    = (__nv_bfloat16*)p;
    cudaGetSymbolAddress(&p, g_Woutb); __nv_bfloat16* Woutb = (__nv_bfloat16*)p;
    cudaGetSymbolAddress(&p, g_Wx);    float*         Wx    = (float*)p;
    cudaGetSymbolAddress(&p, g_hsb);   __nv_bfloat16* hsb   = (__nv_bfloat16*)p;

    cudaFuncSetAttribute(gemm_bf16_kernel,
                         cudaFuncAttributeMaxDynamicSharedMemorySize, GEMM_SMEM);
    cudaFuncSetAttribute(logsoftmax_kernel,
                         cudaFuncAttributeMaxDynamicSharedMemorySize, LSM_SMEM);
    cudaFuncSetAttribute(rnn_cluster_kernel,
                         cudaFuncAttributeMaxDynamicSharedMemorySize, RNN_SMEM);
    cudaFuncSetAttribute(rnn_cluster_kernel,
                         cudaFuncAttributeNonPortableClusterSizeAllowed, 1);

    // weight conversions
    f32_to_bf16_kernel<<<512, 256>>>((const float4*)W,
                                     (__nv_bfloat162*)Wb, (Dd * Dd) / 4);
    f32_to_bf16_kernel<<<512, 256>>>((const float4*)U,
                                     (__nv_bfloat162*)Ub, (Dd * Dd) / 4);
    f32_to_bf16_kernel<<<4096, 256>>>((const float4*)Wout,
                                      (__nv_bfloat162*)Woutb, (Vv * Dd) / 4);
    // embedding gather -> bf16
    gather_embed_kernel<<<Mrows, 128>>>(idx, E, Xb);

    // input projection: Wx = Xb * Wb^T + bW   [2048 x 1024]
    dim3 g1(Mrows / 128, Dd / 128);
    gemm_bf16_kernel<<<g1, 256, GEMM_SMEM>>>(Xb, Wb, bW, Wx, Mrows, Dd, Dd);

    // recurrence: 8 clusters x 16 CTAs, batch-per-cluster, DSMEM h exchange
    rnn_cluster_kernel<<<128, 512, RNN_SMEM>>>(Wx, bU, hsb);

    // output projection: logits = hsb * Woutb^T + bout   [2048 x 32000]
    dim3 g3(Mrows / 128, Vv / 128);
    gemm_bf16_kernel<<<g3, 256, GEMM_SMEM>>>(hsb, Woutb, bout, out, Mrows, Vv, Dd);

    // fused log_softmax
    logsoftmax_kernel<<<Mrows, 256, LSM_SMEM>>>(out);
}